// round 2
// baseline (speedup 1.0000x reference)
#include <cuda_runtime.h>
#include <math.h>

namespace {
constexpr int NB = 4, TE = 256, TD = 512, DM = 512, DI = 1024, DS = 16, DTR = 32, NM = 80;
constexpr int ME = NB * TE;   // 1024 encoder rows
constexpr int MD = NB * TD;   // 2048 decoder rows
}

// ---------------- scratch ----------------
__device__ float g_x0[MD * DM];
__device__ float g_x1[MD * DM];
__device__ float g_xz[MD * 2 * DI];
__device__ float g_u[MD * DI];
__device__ float g_xdbl[MD * 64];
__device__ float g_delta[MD * DI];
__device__ float g_gate[MD * DI];
__device__ float g_im2col[ME * DM * 3];
__device__ float g_wt[DM * 3 * DM];
__device__ float g_h1[ME * DM];
__device__ float g_h2[ME * DM];
__device__ float g_dur[ME];
__device__ int   g_idx[NB * TD];
__device__ float g_mask[NB * TD];

__device__ __forceinline__ float softplus_f(float x) {
    return x > 0.f ? x + log1pf(expf(-x)) : log1pf(expf(x));
}
__device__ __forceinline__ float silu_f(float x) {
    return x / (1.f + expf(-x));
}

// ---------------- embedding ----------------
__global__ void embed_k(const int* __restrict__ text, const float* __restrict__ emb,
                        float* __restrict__ out) {
    int i = blockIdx.x * blockDim.x + threadIdx.x;
    if (i >= ME * DM) return;
    int c = i % DM;
    int r = i / DM;
    out[i] = emb[text[r] * DM + c];
}

// ============ fast double-buffered SGEMM (no bounds checks; M%BM==0, N%BN==0, K%16==0) ============
// EPI: 0=none, 1=softplus(acc+bias), 2=relu(acc+bias)*bn_scale+bn_shift
template<int BM, int BN, int TM, int TN, int EPI>
__global__ __launch_bounds__(256) void fgemm_k(
    const float* __restrict__ A, const float* __restrict__ W, float* __restrict__ C,
    int K, int lda, int ldb, int ldc,
    const float* __restrict__ bias, const float* __restrict__ gamma,
    const float* __restrict__ beta)
{
    constexpr int BK = 16;
    constexpr int TX = BN / TN;
    constexpr int TY = BM / TM;
    static_assert(TX * TY == 256, "thread tiling");
    constexpr int AF4 = (BM * BK) / (256 * 4);  // float4 A-loads per thread (2,1,0)
    constexpr int BF4 = (BN * BK) / (256 * 4);  // float4 B-loads per thread (2,1)
    constexpr int BROWS = 256 / (BN / 4);       // B rows covered per pass

    __shared__ float As[2][BK][BM];
    __shared__ float Bs[2][BK][BN];

    const int tid = threadIdx.x;
    const int tx = tid % TX, ty = tid / TX;
    const int bm = blockIdx.y * BM, bn = blockIdx.x * BN;

    const float* Ag = A + (size_t)bm * lda;
    const float* Wg = W + bn;

    const int arow = tid >> 2, ak = (tid & 3) << 2;  // float4 A path
    const int am_s = tid >> 4, ak_s = tid & 15;      // scalar A path (BM=16)
    const int brow = tid / (BN / 4), bc = (tid % (BN / 4)) * 4;

    float a_pref[AF4 > 0 ? AF4 * 4 : 1];
    float b_pref[BF4 * 4];

    auto g2r = [&](int k0) {
        if constexpr (AF4 > 0) {
            #pragma unroll
            for (int p = 0; p < AF4; p++) {
                float4 v = *reinterpret_cast<const float4*>(
                    Ag + (size_t)(arow + p * 64) * lda + k0 + ak);
                a_pref[p * 4 + 0] = v.x; a_pref[p * 4 + 1] = v.y;
                a_pref[p * 4 + 2] = v.z; a_pref[p * 4 + 3] = v.w;
            }
        } else {
            a_pref[0] = Ag[(size_t)am_s * lda + k0 + ak_s];
        }
        #pragma unroll
        for (int p = 0; p < BF4; p++) {
            float4 v = *reinterpret_cast<const float4*>(
                Wg + (size_t)(k0 + brow + p * BROWS) * ldb + bc);
            b_pref[p * 4 + 0] = v.x; b_pref[p * 4 + 1] = v.y;
            b_pref[p * 4 + 2] = v.z; b_pref[p * 4 + 3] = v.w;
        }
    };
    auto r2s = [&](int buf) {
        if constexpr (AF4 > 0) {
            #pragma unroll
            for (int p = 0; p < AF4; p++)
                #pragma unroll
                for (int j = 0; j < 4; j++)
                    As[buf][ak + j][arow + p * 64] = a_pref[p * 4 + j];
        } else {
            As[buf][ak_s][am_s] = a_pref[0];
        }
        #pragma unroll
        for (int p = 0; p < BF4; p++)
            *reinterpret_cast<float4*>(&Bs[buf][brow + p * BROWS][bc]) =
                make_float4(b_pref[p * 4 + 0], b_pref[p * 4 + 1],
                            b_pref[p * 4 + 2], b_pref[p * 4 + 3]);
    };

    float acc[TM][TN] = {};
    const int KB = K / BK;
    g2r(0);
    r2s(0);
    __syncthreads();
    for (int kb = 0; kb < KB; kb++) {
        const int cur = kb & 1;
        if (kb + 1 < KB) g2r((kb + 1) * BK);
        #pragma unroll
        for (int kk = 0; kk < BK; kk++) {
            float af[TM], bf[TN];
            #pragma unroll
            for (int i = 0; i < TM; i++) af[i] = As[cur][kk][ty * TM + i];
            #pragma unroll
            for (int j = 0; j < TN; j++) bf[j] = Bs[cur][kk][tx * TN + j];
            #pragma unroll
            for (int i = 0; i < TM; i++)
                #pragma unroll
                for (int j = 0; j < TN; j++)
                    acc[i][j] = fmaf(af[i], bf[j], acc[i][j]);
        }
        if (kb + 1 < KB) r2s(1 - cur);
        __syncthreads();
    }

    #pragma unroll
    for (int i = 0; i < TM; i++) {
        const int m = bm + ty * TM + i;
        #pragma unroll
        for (int j = 0; j < TN; j += 4) {
            float4 v;
            float* pv = &v.x;
            #pragma unroll
            for (int q = 0; q < 4; q++) {
                const int n = bn + tx * TN + j + q;
                float x = acc[i][j + q];
                if (EPI == 1) x = softplus_f(x + bias[n]);
                else if (EPI == 2)
                    x = fmaxf(x + bias[n], 0.f) * (gamma[n] * rsqrtf(1.f + 1e-5f)) + beta[n];
                pv[q] = x;
            }
            *reinterpret_cast<float4*>(C + (size_t)m * ldc + bn + tx * TN + j) = v;
        }
    }
}

// ---------------- small bounds-checked GEMM for mel projection (N=80) ----------------
__global__ __launch_bounds__(256) void melgemm_k(
    const float* __restrict__ A, const float* __restrict__ W, float* __restrict__ C,
    int M, int N, int K, int lda, int ldb, int ldc, const float* __restrict__ rmask)
{
    __shared__ float As[16][64];
    __shared__ float Bs[16][64];
    const int bm = blockIdx.y * 64, bn = blockIdx.x * 64;
    const int tid = threadIdx.x;
    const int tx = tid & 15, ty = tid >> 4;
    const int am = tid >> 2, ak = (tid & 3) << 2;
    const int bk = tid >> 4, bn4 = (tid & 15) << 2;
    float acc[4][4] = {};
    for (int k0 = 0; k0 < K; k0 += 16) {
        float4 av = make_float4(0.f, 0.f, 0.f, 0.f);
        if (bm + am < M)
            av = *reinterpret_cast<const float4*>(A + (size_t)(bm + am) * lda + k0 + ak);
        As[ak + 0][am] = av.x; As[ak + 1][am] = av.y;
        As[ak + 2][am] = av.z; As[ak + 3][am] = av.w;
        float4 bv;
        const float* wr = W + (size_t)(k0 + bk) * ldb;
        bv.x = (bn + bn4 + 0 < N) ? wr[bn + bn4 + 0] : 0.f;
        bv.y = (bn + bn4 + 1 < N) ? wr[bn + bn4 + 1] : 0.f;
        bv.z = (bn + bn4 + 2 < N) ? wr[bn + bn4 + 2] : 0.f;
        bv.w = (bn + bn4 + 3 < N) ? wr[bn + bn4 + 3] : 0.f;
        Bs[bk][bn4 + 0] = bv.x; Bs[bk][bn4 + 1] = bv.y;
        Bs[bk][bn4 + 2] = bv.z; Bs[bk][bn4 + 3] = bv.w;
        __syncthreads();
        #pragma unroll
        for (int kk = 0; kk < 16; kk++) {
            float af[4], bf[4];
            #pragma unroll
            for (int i = 0; i < 4; i++) af[i] = As[kk][(ty << 2) + i];
            #pragma unroll
            for (int j = 0; j < 4; j++) bf[j] = Bs[kk][(tx << 2) + j];
            #pragma unroll
            for (int i = 0; i < 4; i++)
                #pragma unroll
                for (int j = 0; j < 4; j++)
                    acc[i][j] = fmaf(af[i], bf[j], acc[i][j]);
        }
        __syncthreads();
    }
    #pragma unroll
    for (int i = 0; i < 4; i++) {
        int m = bm + (ty << 2) + i;
        if (m >= M) continue;
        #pragma unroll
        for (int j = 0; j < 4; j++) {
            int n = bn + (tx << 2) + j;
            if (n >= N) continue;
            C[(size_t)m * ldc + n] = acc[i][j] * rmask[m];
        }
    }
}

// ---------------- depthwise causal conv (K=4) + SiLU ----------------
__global__ void dwconv_silu_k(const float* __restrict__ xz, const float* __restrict__ w,
                              const float* __restrict__ bcv, float* __restrict__ u, int L) {
    int i = blockIdx.x * blockDim.x + threadIdx.x;
    int total = NB * L * DI;
    if (i >= total) return;
    int d = i % DI;
    int bt = i / DI;
    int t = bt % L;
    int bb = bt / L;
    float acc = bcv[d];
    const float* wr = w + d * 4;
    #pragma unroll
    for (int k = 0; k < 4; k++) {
        int ts = t - 3 + k;
        if (ts >= 0)
            acc = fmaf(wr[k], xz[((size_t)(bb * L + ts)) * 2048 + d], acc);
    }
    u[i] = silu_f(acc);
}

// ---------------- selective scan ----------------
__global__ void scan_k(const float* __restrict__ xdbl, const float* __restrict__ delta,
                       const float* __restrict__ u, const float* __restrict__ xz,
                       const float* __restrict__ Alog, const float* __restrict__ Dp,
                       float* __restrict__ gate, int L) {
    int gt = blockIdx.x * blockDim.x + threadIdx.x;
    if (gt >= NB * DI * 4) return;
    int lane = gt & 3;
    int gid = gt >> 2;
    int d = gid % DI;
    int bb = gid / DI;
    float a0 = -expf(Alog[d * DS + lane * 4 + 0]);
    float a1 = -expf(Alog[d * DS + lane * 4 + 1]);
    float a2 = -expf(Alog[d * DS + lane * 4 + 2]);
    float a3 = -expf(Alog[d * DS + lane * 4 + 3]);
    float Dd = Dp[d];
    float h0 = 0.f, h1 = 0.f, h2 = 0.f, h3 = 0.f;
    for (int t = 0; t < L; t++) {
        size_t row = (size_t)bb * L + t;
        float dl = delta[row * DI + d];
        float ut = u[row * DI + d];
        float du = dl * ut;
        const float* xd = xdbl + row * 64;
        float4 Bv = *reinterpret_cast<const float4*>(xd + 32 + lane * 4);
        float4 Cv = *reinterpret_cast<const float4*>(xd + 48 + lane * 4);
        h0 = fmaf(__expf(dl * a0), h0, du * Bv.x);
        h1 = fmaf(__expf(dl * a1), h1, du * Bv.y);
        h2 = fmaf(__expf(dl * a2), h2, du * Bv.z);
        h3 = fmaf(__expf(dl * a3), h3, du * Bv.w);
        float y = h0 * Cv.x + h1 * Cv.y + h2 * Cv.z + h3 * Cv.w;
        y += __shfl_xor_sync(0xffffffffu, y, 1);
        y += __shfl_xor_sync(0xffffffffu, y, 2);
        if (lane == 0) {
            float res = xz[row * 2048 + 1024 + d];
            gate[row * DI + d] = (y + ut * Dd) * silu_f(res);
        }
    }
}

// ---------------- duration predictor helpers ----------------
__global__ void wt_k(const float* __restrict__ w, float* __restrict__ wt) {
    int i = blockIdx.x * blockDim.x + threadIdx.x;
    if (i >= DM * DM * 3) return;
    int k = i % 3;
    int c = (i / 3) % DM;
    int d = i / (3 * DM);
    wt[(size_t)(k * DM + c) * DM + d] = w[i];
}
__global__ void im2col_k(const float* __restrict__ src, float* __restrict__ dst) {
    int i = blockIdx.x * blockDim.x + threadIdx.x;
    if (i >= ME * DM * 3) return;
    int c = i % DM;
    int k = (i / DM) % 3;
    int r = i / (DM * 3);
    int t = r % TE;
    int ts = t - 1 + k;
    float v = 0.f;
    if (ts >= 0 && ts < TE) v = src[(size_t)(r - t + ts) * DM + c];
    dst[i] = v;
}
__global__ void dur_k(const float* __restrict__ h2, const float* __restrict__ w3,
                      const float* __restrict__ b3, float* __restrict__ dur) {
    int warp = (blockIdx.x * blockDim.x + threadIdx.x) >> 5;
    int lane = threadIdx.x & 31;
    if (warp >= ME) return;
    const float* hr = h2 + (size_t)warp * DM;
    float s = 0.f;
    for (int c = lane; c < DM; c += 32) s = fmaf(hr[c], w3[c], s);
    #pragma unroll
    for (int o = 16; o; o >>= 1) s += __shfl_xor_sync(0xffffffffu, s, o);
    if (lane == 0) dur[warp] = softplus_f(s + b3[0]);
}

// ---------------- length regulator ----------------
__global__ void expand_k(const float* __restrict__ dur, int* __restrict__ idx,
                         float* __restrict__ mask) {
    __shared__ float ends[TE];
    int bb = blockIdx.x;
    int t = threadIdx.x;
    ends[t] = rintf(fmaxf(dur[bb * TE + t], 0.f));
    __syncthreads();
    if (t == 0) {
        float s = 0.f;
        for (int i = 0; i < TE; i++) { s += ends[i]; ends[i] = s; }
    }
    __syncthreads();
    float total = ends[TE - 1];
    for (int tp = t; tp < TD; tp += TE) {
        float fp = (float)tp;
        int lo = 0, hi = TE;
        while (lo < hi) { int mid = (lo + hi) >> 1; if (ends[mid] <= fp) lo = mid + 1; else hi = mid; }
        int id = lo < TE - 1 ? lo : TE - 1;
        idx[bb * TD + tp] = id;
        mask[bb * TD + tp] = fp < total ? 1.f : 0.f;
    }
}
__global__ void gather_k(const float* __restrict__ enc, const int* __restrict__ idx,
                         const float* __restrict__ mask, float* __restrict__ out) {
    int i = blockIdx.x * blockDim.x + threadIdx.x;
    if (i >= MD * DM) return;
    int c = i % DM;
    int r = i / DM;
    int bb = r / TD;
    out[i] = enc[(size_t)(bb * TE + idx[r]) * DM + c] * mask[r];
}

// ---------------- rmsnorm ----------------
__global__ void rmsnorm_k(const float* __restrict__ x, const float* __restrict__ g,
                          float* __restrict__ out) {
    int r = blockIdx.x;
    const float* xr = x + (size_t)r * DM;
    float s = 0.f;
    for (int c = threadIdx.x; c < DM; c += blockDim.x) { float v = xr[c]; s = fmaf(v, v, s); }
    __shared__ float red[4];
    #pragma unroll
    for (int o = 16; o; o >>= 1) s += __shfl_xor_sync(0xffffffffu, s, o);
    int w = threadIdx.x >> 5;
    if ((threadIdx.x & 31) == 0) red[w] = s;
    __syncthreads();
    if (threadIdx.x == 0) red[0] = red[0] + red[1] + red[2] + red[3];
    __syncthreads();
    float scale = rsqrtf(red[0] / (float)DM + 1e-6f);
    for (int c = threadIdx.x; c < DM; c += blockDim.x)
        out[(size_t)r * DM + c] = xr[c] * scale * g[c];
}

__global__ void tail_k(float* __restrict__ out, const float* __restrict__ mask, int n) {
    int i = blockIdx.x * blockDim.x + threadIdx.x;
    if (i >= n) return;
    out[i] = (i < NB * TD) ? mask[i] : 0.f;
}

// ---------------- host driver ----------------
extern "C" void kernel_launch(void* const* d_in, const int* in_sizes, int n_in,
                              void* d_out, int out_size) {
    (void)n_in;
    int map[32];
    if (in_sizes[2] == 3 * DM * 2 * DI) {
        for (int i = 0; i < 32; i++) map[i] = i;
    } else {
        const int m[32] = {0, 1,
                           14, 15, 16, 17, 18, 19, 20, 21, 22,
                           2, 3, 4, 5, 6, 7, 8, 9, 10, 11,
                           23, 24, 25, 26, 27, 28, 29, 30, 31,
                           12, 13};
        for (int i = 0; i < 32; i++) map[i] = m[i];
    }
    const int*   text      = (const int*)  d_in[map[0]];
    const float* emb       = (const float*)d_in[map[1]];
    const float* enc_in_w  = (const float*)d_in[map[2]];
    const float* enc_cw    = (const float*)d_in[map[3]];
    const float* enc_cb    = (const float*)d_in[map[4]];
    const float* enc_xpw   = (const float*)d_in[map[5]];
    const float* enc_dtw   = (const float*)d_in[map[6]];
    const float* enc_dtb   = (const float*)d_in[map[7]];
    const float* enc_alog  = (const float*)d_in[map[8]];
    const float* enc_dp    = (const float*)d_in[map[9]];
    const float* enc_ow    = (const float*)d_in[map[10]];
    const float* dp_c1w    = (const float*)d_in[map[11]];
    const float* dp_c1b    = (const float*)d_in[map[12]];
    const float* dp_g1     = (const float*)d_in[map[13]];
    const float* dp_b1     = (const float*)d_in[map[14]];
    const float* dp_c2w    = (const float*)d_in[map[15]];
    const float* dp_c2b    = (const float*)d_in[map[16]];
    const float* dp_g2     = (const float*)d_in[map[17]];
    const float* dp_b2     = (const float*)d_in[map[18]];
    const float* dp_c3w    = (const float*)d_in[map[19]];
    const float* dp_c3b    = (const float*)d_in[map[20]];
    const float* dec_in_w  = (const float*)d_in[map[21]];
    const float* dec_cw    = (const float*)d_in[map[22]];
    const float* dec_cb    = (const float*)d_in[map[23]];
    const float* dec_xpw   = (const float*)d_in[map[24]];
    const float* dec_dtw   = (const float*)d_in[map[25]];
    const float* dec_dtb   = (const float*)d_in[map[26]];
    const float* dec_alog  = (const float*)d_in[map[27]];
    const float* dec_dpv   = (const float*)d_in[map[28]];
    const float* dec_ow    = (const float*)d_in[map[29]];
    const float* norm_g    = (const float*)d_in[map[30]];
    const float* out_w     = (const float*)d_in[map[31]];

    float *x0, *x1, *xz, *u, *xdbl, *delta, *gate, *im, *wt, *h1, *h2, *dur, *mask;
    int* idx;
    cudaGetSymbolAddress((void**)&x0,    g_x0);
    cudaGetSymbolAddress((void**)&x1,    g_x1);
    cudaGetSymbolAddress((void**)&xz,    g_xz);
    cudaGetSymbolAddress((void**)&u,     g_u);
    cudaGetSymbolAddress((void**)&xdbl,  g_xdbl);
    cudaGetSymbolAddress((void**)&delta, g_delta);
    cudaGetSymbolAddress((void**)&gate,  g_gate);
    cudaGetSymbolAddress((void**)&im,    g_im2col);
    cudaGetSymbolAddress((void**)&wt,    g_wt);
    cudaGetSymbolAddress((void**)&h1,    g_h1);
    cudaGetSymbolAddress((void**)&h2,    g_h2);
    cudaGetSymbolAddress((void**)&dur,   g_dur);
    cudaGetSymbolAddress((void**)&idx,   g_idx);
    cudaGetSymbolAddress((void**)&mask,  g_mask);

    auto mamba = [&](const float* xin, float* xout, int L, int l,
                     const float* inw, const float* cw, const float* cb,
                     const float* xpw, const float* dtw, const float* dtb,
                     const float* alog, const float* dp, const float* ow) {
        int M = NB * L;
        // in_proj: [M,512] @ [512,2048]
        fgemm_k<128, 128, 8, 8, 0><<<dim3(2 * DI / 128, M / 128), 256>>>(
            xin, inw + (size_t)l * DM * 2 * DI, xz, DM, DM, 2 * DI, 2 * DI,
            nullptr, nullptr, nullptr);
        int tot = M * DI;
        dwconv_silu_k<<<(tot + 255) / 256, 256>>>(xz, cw + (size_t)l * DI * 4,
                                                  cb + (size_t)l * DI, u, L);
        // xproj: [M,1024] @ [1024,64]
        fgemm_k<16, 64, 1, 4, 0><<<dim3(1, M / 16), 256>>>(
            u, xpw + (size_t)l * DI * 64, xdbl, DI, DI, 64, 64,
            nullptr, nullptr, nullptr);
        // dt: softplus([M,32] @ [32,1024] + b)
        fgemm_k<128, 128, 8, 8, 1><<<dim3(DI / 128, M / 128), 256>>>(
            xdbl, dtw + (size_t)l * DTR * DI, delta, DTR, 64, DI, DI,
            dtb + (size_t)l * DI, nullptr, nullptr);
        scan_k<<<(NB * DI * 4 + 127) / 128, 128>>>(xdbl, delta, u, xz,
                                                   alog + (size_t)l * DI * DS,
                                                   dp + (size_t)l * DI, gate, L);
        // out_proj: [M,1024] @ [1024,512]
        fgemm_k<64, 128, 4, 8, 0><<<dim3(DM / 128, M / 64), 256>>>(
            gate, ow + (size_t)l * DI * DM, xout, DI, DI, DM, DM,
            nullptr, nullptr, nullptr);
    };

    embed_k<<<(ME * DM + 255) / 256, 256>>>(text, emb, x0);

    mamba(x0, x1, TE, 0, enc_in_w, enc_cw, enc_cb, enc_xpw, enc_dtw, enc_dtb, enc_alog, enc_dp, enc_ow);
    mamba(x1, x0, TE, 1, enc_in_w, enc_cw, enc_cb, enc_xpw, enc_dtw, enc_dtb, enc_alog, enc_dp, enc_ow);
    mamba(x0, x1, TE, 2, enc_in_w, enc_cw, enc_cb, enc_xpw, enc_dtw, enc_dtb, enc_alog, enc_dp, enc_ow);

    // duration predictor on x1
    wt_k<<<(DM * DM * 3 + 255) / 256, 256>>>(dp_c1w, wt);
    im2col_k<<<(ME * DM * 3 + 255) / 256, 256>>>(x1, im);
    fgemm_k<64, 128, 4, 8, 2><<<dim3(DM / 128, ME / 64), 256>>>(
        im, wt, h1, 3 * DM, 3 * DM, DM, DM, dp_c1b, dp_g1, dp_b1);
    wt_k<<<(DM * DM * 3 + 255) / 256, 256>>>(dp_c2w, wt);
    im2col_k<<<(ME * DM * 3 + 255) / 256, 256>>>(h1, im);
    fgemm_k<64, 128, 4, 8, 2><<<dim3(DM / 128, ME / 64), 256>>>(
        im, wt, h2, 3 * DM, 3 * DM, DM, DM, dp_c2b, dp_g2, dp_b2);
    dur_k<<<(ME * 32 + 255) / 256, 256>>>(h2, dp_c3w, dp_c3b, dur);

    expand_k<<<NB, TE>>>(dur, idx, mask);
    gather_k<<<(MD * DM + 255) / 256, 256>>>(x1, idx, mask, x0);

    mamba(x0, x1, TD, 0, dec_in_w, dec_cw, dec_cb, dec_xpw, dec_dtw, dec_dtb, dec_alog, dec_dpv, dec_ow);
    mamba(x1, x0, TD, 1, dec_in_w, dec_cw, dec_cb, dec_xpw, dec_dtw, dec_dtb, dec_alog, dec_dpv, dec_ow);
    mamba(x0, x1, TD, 2, dec_in_w, dec_cw, dec_cb, dec_xpw, dec_dtw, dec_dtb, dec_alog, dec_dpv, dec_ow);

    rmsnorm_k<<<MD, 128>>>(x1, norm_g, x0);
    melgemm_k<<<dim3((NM + 63) / 64, MD / 64), 256>>>(
        x0, out_w, (float*)d_out, MD, NM, DM, DM, NM, NM, mask);

    int melN = MD * NM;
    if (out_size > melN) {
        int n = out_size - melN;
        tail_k<<<(n + 255) / 256, 256>>>((float*)d_out + melN, mask, n);
    }
}

// round 3
// speedup vs baseline: 1.7311x; 1.7311x over previous
#include <cuda_runtime.h>
#include <math.h>

namespace {
constexpr int NB = 4, TE = 256, TD = 512, DM = 512, DI = 1024, DS = 16, DTR = 32, NM = 80;
constexpr int ME = NB * TE;   // 1024 encoder rows
constexpr int MD = NB * TD;   // 2048 decoder rows
constexpr int KS = 8;         // xproj split-K factor
}

// ---------------- scratch ----------------
__device__ float g_x0[MD * DM];
__device__ float g_x1[MD * DM];
__device__ float g_xz[MD * 2 * DI];
__device__ float g_u[MD * DI];
__device__ float g_xdbl[MD * 64];
__device__ float g_part[KS * MD * 64];
__device__ float g_delta[MD * DI];
__device__ float g_gate[MD * DI];
__device__ float g_im2col[ME * DM * 3];
__device__ float g_wt[DM * 3 * DM];
__device__ float g_h1[ME * DM];
__device__ float g_h2[ME * DM];
__device__ float g_dur[ME];
__device__ int   g_idx[NB * TD];
__device__ float g_mask[NB * TD];

__device__ __forceinline__ float softplus_f(float x) {
    return x > 0.f ? x + log1pf(expf(-x)) : log1pf(expf(x));
}
__device__ __forceinline__ float silu_f(float x) {
    return x / (1.f + expf(-x));
}

// ---------------- embedding ----------------
__global__ void embed_k(const int* __restrict__ text, const float* __restrict__ emb,
                        float* __restrict__ out) {
    int i = blockIdx.x * blockDim.x + threadIdx.x;
    if (i >= ME * DM) return;
    int c = i % DM;
    int r = i / DM;
    out[i] = emb[text[r] * DM + c];
}

// ============ gemm128: 128x128 block, BK=8, 256 thr, 8x8/thread, double-buffered ============
// conflict-free layout: fragments at ty*4 / ty*4+64 (rows), tx*4 / tx*4+64 (cols)
// EPI: 0=none
template<int EPI>
__global__ __launch_bounds__(256, 2) void gemm128_k(
    const float* __restrict__ A, const float* __restrict__ W, float* __restrict__ C,
    int K, int lda, int ldb, int ldc, const float* __restrict__ bias)
{
    __shared__ float As[2][8][128];
    __shared__ float Bs[2][8][128];
    const int tid = threadIdx.x;
    const int tx = tid & 15, ty = tid >> 4;
    const int bm = blockIdx.y * 128, bn = blockIdx.x * 128;
    const int ar = tid >> 1, ac = (tid & 1) << 2;     // A: row tid/2, col (tid%2)*4
    const int br = tid >> 5, bc = (tid & 31) << 2;    // B: row tid/32, col (tid%32)*4
    const float* Ag = A + (size_t)(bm + ar) * lda + ac;
    const float* Wg = W + bn + bc;

    float4 ap, bp;
    auto ld = [&](int k0) {
        ap = *reinterpret_cast<const float4*>(Ag + k0);
        bp = *reinterpret_cast<const float4*>(Wg + (size_t)(k0 + br) * ldb);
    };
    auto st = [&](int buf) {
        As[buf][ac + 0][ar] = ap.x; As[buf][ac + 1][ar] = ap.y;
        As[buf][ac + 2][ar] = ap.z; As[buf][ac + 3][ar] = ap.w;
        *reinterpret_cast<float4*>(&Bs[buf][br][bc]) = bp;
    };

    float acc[8][8] = {};
    const int KB = K / 8;
    ld(0); st(0); __syncthreads();
    for (int kb = 0; kb < KB; kb++) {
        const int cur = kb & 1;
        if (kb + 1 < KB) ld((kb + 1) * 8);
        #pragma unroll
        for (int kk = 0; kk < 8; kk++) {
            float a[8], b[8];
            *reinterpret_cast<float4*>(&a[0]) = *reinterpret_cast<const float4*>(&As[cur][kk][ty * 4]);
            *reinterpret_cast<float4*>(&a[4]) = *reinterpret_cast<const float4*>(&As[cur][kk][ty * 4 + 64]);
            *reinterpret_cast<float4*>(&b[0]) = *reinterpret_cast<const float4*>(&Bs[cur][kk][tx * 4]);
            *reinterpret_cast<float4*>(&b[4]) = *reinterpret_cast<const float4*>(&Bs[cur][kk][tx * 4 + 64]);
            #pragma unroll
            for (int i = 0; i < 8; i++)
                #pragma unroll
                for (int j = 0; j < 8; j++)
                    acc[i][j] = fmaf(a[i], b[j], acc[i][j]);
        }
        if (kb + 1 < KB) st(1 - cur);
        __syncthreads();
    }

    #pragma unroll
    for (int ih = 0; ih < 2; ih++) {
        #pragma unroll
        for (int i = 0; i < 4; i++) {
            const int m = bm + ty * 4 + ih * 64 + i;
            #pragma unroll
            for (int jh = 0; jh < 2; jh++) {
                const int n0 = bn + tx * 4 + jh * 64;
                float4 v;
                v.x = acc[ih * 4 + i][jh * 4 + 0];
                v.y = acc[ih * 4 + i][jh * 4 + 1];
                v.z = acc[ih * 4 + i][jh * 4 + 2];
                v.w = acc[ih * 4 + i][jh * 4 + 3];
                *reinterpret_cast<float4*>(C + (size_t)m * ldc + n0) = v;
            }
        }
    }
}

// ============ gemm64: 64x64 block, BK=16, 256 thr, 4x4/thread ============
// EPI: 0=none, 1=softplus(acc+bias), 2=relu(acc+bias)*bn_scale+bn_shift
template<int EPI>
__global__ __launch_bounds__(256) void gemm64_k(
    const float* __restrict__ A, const float* __restrict__ W, float* __restrict__ C,
    int K, int lda, int ldb, int ldc,
    const float* __restrict__ bias, const float* __restrict__ gamma,
    const float* __restrict__ beta)
{
    __shared__ float As[2][16][64];
    __shared__ float Bs[2][16][64];
    const int tid = threadIdx.x;
    const int tx = tid & 15, ty = tid >> 4;
    const int bm = blockIdx.y * 64, bn = blockIdx.x * 64;
    const int ar = tid >> 2, ac = (tid & 3) << 2;     // A: 64 rows x 16 cols
    const int br = tid >> 4, bc = (tid & 15) << 2;    // B: 16 rows x 64 cols
    const float* Ag = A + (size_t)(bm + ar) * lda + ac;
    const float* Wg = W + bn + bc;

    float4 ap, bp;
    auto ld = [&](int k0) {
        ap = *reinterpret_cast<const float4*>(Ag + k0);
        bp = *reinterpret_cast<const float4*>(Wg + (size_t)(k0 + br) * ldb);
    };
    auto st = [&](int buf) {
        As[buf][ac + 0][ar] = ap.x; As[buf][ac + 1][ar] = ap.y;
        As[buf][ac + 2][ar] = ap.z; As[buf][ac + 3][ar] = ap.w;
        *reinterpret_cast<float4*>(&Bs[buf][br][bc]) = bp;
    };

    float acc[4][4] = {};
    const int KB = K / 16;
    ld(0); st(0); __syncthreads();
    for (int kb = 0; kb < KB; kb++) {
        const int cur = kb & 1;
        if (kb + 1 < KB) ld((kb + 1) * 16);
        #pragma unroll
        for (int kk = 0; kk < 16; kk++) {
            float a[4], b[4];
            *reinterpret_cast<float4*>(a) = *reinterpret_cast<const float4*>(&As[cur][kk][ty * 4]);
            *reinterpret_cast<float4*>(b) = *reinterpret_cast<const float4*>(&Bs[cur][kk][tx * 4]);
            #pragma unroll
            for (int i = 0; i < 4; i++)
                #pragma unroll
                for (int j = 0; j < 4; j++)
                    acc[i][j] = fmaf(a[i], b[j], acc[i][j]);
        }
        if (kb + 1 < KB) st(1 - cur);
        __syncthreads();
    }

    #pragma unroll
    for (int i = 0; i < 4; i++) {
        const int m = bm + ty * 4 + i;
        const int n0 = bn + tx * 4;
        float4 v;
        float* pv = &v.x;
        #pragma unroll
        for (int q = 0; q < 4; q++) {
            float x = acc[i][q];
            if (EPI == 1) x = softplus_f(x + bias[n0 + q]);
            else if (EPI == 2)
                x = fmaxf(x + bias[n0 + q], 0.f) * (gamma[n0 + q] * rsqrtf(1.f + 1e-5f)) + beta[n0 + q];
            pv[q] = x;
        }
        *reinterpret_cast<float4*>(C + (size_t)m * ldc + n0) = v;
    }
}

// ============ xproj split-K: per block 64 rows x 64 cols x (K/KS) slice ============
__global__ __launch_bounds__(256) void xp_k(
    const float* __restrict__ A, const float* __restrict__ W, float* __restrict__ P, int M)
{
    __shared__ float As[2][16][64];
    __shared__ float Bs[2][16][64];
    const int tid = threadIdx.x;
    const int tx = tid & 15, ty = tid >> 4;
    const int bm = blockIdx.x * 64;
    const int kz = blockIdx.y;                        // 0..KS-1
    const int kbase = kz * (DI / KS);                 // 128 per slice
    const int ar = tid >> 2, ac = (tid & 3) << 2;
    const int br = tid >> 4, bc = (tid & 15) << 2;
    const float* Ag = A + (size_t)(bm + ar) * DI + kbase + ac;
    const float* Wg = W + (size_t)kbase * 64 + bc;

    float4 ap, bp;
    auto ld = [&](int k0) {
        ap = *reinterpret_cast<const float4*>(Ag + k0);
        bp = *reinterpret_cast<const float4*>(Wg + (size_t)(k0 + br) * 64);
    };
    auto st = [&](int buf) {
        As[buf][ac + 0][ar] = ap.x; As[buf][ac + 1][ar] = ap.y;
        As[buf][ac + 2][ar] = ap.z; As[buf][ac + 3][ar] = ap.w;
        *reinterpret_cast<float4*>(&Bs[buf][br][bc]) = bp;
    };

    float acc[4][4] = {};
    const int KB = (DI / KS) / 16;   // 8
    ld(0); st(0); __syncthreads();
    for (int kb = 0; kb < KB; kb++) {
        const int cur = kb & 1;
        if (kb + 1 < KB) ld((kb + 1) * 16);
        #pragma unroll
        for (int kk = 0; kk < 16; kk++) {
            float a[4], b[4];
            *reinterpret_cast<float4*>(a) = *reinterpret_cast<const float4*>(&As[cur][kk][ty * 4]);
            *reinterpret_cast<float4*>(b) = *reinterpret_cast<const float4*>(&Bs[cur][kk][tx * 4]);
            #pragma unroll
            for (int i = 0; i < 4; i++)
                #pragma unroll
                for (int j = 0; j < 4; j++)
                    acc[i][j] = fmaf(a[i], b[j], acc[i][j]);
        }
        if (kb + 1 < KB) st(1 - cur);
        __syncthreads();
    }
    float* Pg = P + ((size_t)kz * M + bm) * 64;
    #pragma unroll
    for (int i = 0; i < 4; i++) {
        float4 v = make_float4(acc[i][0], acc[i][1], acc[i][2], acc[i][3]);
        *reinterpret_cast<float4*>(Pg + (size_t)(ty * 4 + i) * 64 + tx * 4) = v;
    }
}

__global__ void xp_reduce_k(const float* __restrict__ P, float* __restrict__ out, int M) {
    int i = blockIdx.x * blockDim.x + threadIdx.x;   // M*16 threads, float4 each
    if (i >= M * 16) return;
    float4 s = make_float4(0.f, 0.f, 0.f, 0.f);
    #pragma unroll
    for (int z = 0; z < KS; z++) {
        float4 v = *reinterpret_cast<const float4*>(P + ((size_t)z * M * 16 + i) * 4);
        s.x += v.x; s.y += v.y; s.z += v.z; s.w += v.w;
    }
    *reinterpret_cast<float4*>(out + (size_t)i * 4) = s;
}

// ---------------- depthwise causal conv (K=4) + SiLU ----------------
__global__ void dwconv_silu_k(const float* __restrict__ xz, const float* __restrict__ w,
                              const float* __restrict__ bcv, float* __restrict__ u, int L) {
    int i = blockIdx.x * blockDim.x + threadIdx.x;
    int total = NB * L * DI;
    if (i >= total) return;
    int d = i % DI;
    int bt = i / DI;
    int t = bt % L;
    int bb = bt / L;
    float acc = bcv[d];
    const float* wr = w + d * 4;
    #pragma unroll
    for (int k = 0; k < 4; k++) {
        int ts = t - 3 + k;
        if (ts >= 0)
            acc = fmaf(wr[k], xz[((size_t)(bb * L + ts)) * 2048 + d], acc);
    }
    u[i] = silu_f(acc);
}

// ---------------- selective scan with next-step prefetch ----------------
__global__ void scan_k(const float* __restrict__ xdbl, const float* __restrict__ delta,
                       const float* __restrict__ u, const float* __restrict__ xz,
                       const float* __restrict__ Alog, const float* __restrict__ Dp,
                       float* __restrict__ gate, int L) {
    int gt = blockIdx.x * blockDim.x + threadIdx.x;
    if (gt >= NB * DI * 4) return;
    int lane = gt & 3;
    int gid = gt >> 2;
    int d = gid % DI;
    int bb = gid / DI;
    float a0 = -expf(Alog[d * DS + lane * 4 + 0]);
    float a1 = -expf(Alog[d * DS + lane * 4 + 1]);
    float a2 = -expf(Alog[d * DS + lane * 4 + 2]);
    float a3 = -expf(Alog[d * DS + lane * 4 + 3]);
    float Dd = Dp[d];
    float h0 = 0.f, h1 = 0.f, h2 = 0.f, h3 = 0.f;

    float dl, ut, rs;
    float4 Bv, Cv;
    auto loadt = [&](int t, float& dl_, float& ut_, float4& B_, float4& C_, float& rs_) {
        size_t row = (size_t)bb * L + t;
        dl_ = delta[row * DI + d];
        ut_ = u[row * DI + d];
        const float* xd = xdbl + row * 64;
        B_ = *reinterpret_cast<const float4*>(xd + 32 + lane * 4);
        C_ = *reinterpret_cast<const float4*>(xd + 48 + lane * 4);
        rs_ = xz[row * 2048 + 1024 + d];
    };
    loadt(0, dl, ut, Bv, Cv, rs);
    for (int t = 0; t < L; t++) {
        float dl2, ut2, rs2;
        float4 Bv2, Cv2;
        if (t + 1 < L) loadt(t + 1, dl2, ut2, Bv2, Cv2, rs2);
        float du = dl * ut;
        h0 = fmaf(__expf(dl * a0), h0, du * Bv.x);
        h1 = fmaf(__expf(dl * a1), h1, du * Bv.y);
        h2 = fmaf(__expf(dl * a2), h2, du * Bv.z);
        h3 = fmaf(__expf(dl * a3), h3, du * Bv.w);
        float y = h0 * Cv.x + h1 * Cv.y + h2 * Cv.z + h3 * Cv.w;
        y += __shfl_xor_sync(0xffffffffu, y, 1);
        y += __shfl_xor_sync(0xffffffffu, y, 2);
        if (lane == 0) {
            size_t row = (size_t)bb * L + t;
            gate[row * DI + d] = (y + ut * Dd) * silu_f(rs);
        }
        dl = dl2; ut = ut2; Bv = Bv2; Cv = Cv2; rs = rs2;
    }
}

// ---------------- duration predictor helpers ----------------
__global__ void wt_k(const float* __restrict__ w, float* __restrict__ wt) {
    int i = blockIdx.x * blockDim.x + threadIdx.x;
    if (i >= DM * DM * 3) return;
    int k = i % 3;
    int c = (i / 3) % DM;
    int d = i / (3 * DM);
    wt[(size_t)(k * DM + c) * DM + d] = w[i];
}
__global__ void im2col_k(const float* __restrict__ src, float* __restrict__ dst) {
    int i = blockIdx.x * blockDim.x + threadIdx.x;
    if (i >= ME * DM * 3) return;
    int c = i % DM;
    int k = (i / DM) % 3;
    int r = i / (DM * 3);
    int t = r % TE;
    int ts = t - 1 + k;
    float v = 0.f;
    if (ts >= 0 && ts < TE) v = src[(size_t)(r - t + ts) * DM + c];
    dst[i] = v;
}
__global__ void dur_k(const float* __restrict__ h2, const float* __restrict__ w3,
                      const float* __restrict__ b3, float* __restrict__ dur) {
    int warp = (blockIdx.x * blockDim.x + threadIdx.x) >> 5;
    int lane = threadIdx.x & 31;
    if (warp >= ME) return;
    const float* hr = h2 + (size_t)warp * DM;
    float s = 0.f;
    for (int c = lane; c < DM; c += 32) s = fmaf(hr[c], w3[c], s);
    #pragma unroll
    for (int o = 16; o; o >>= 1) s += __shfl_xor_sync(0xffffffffu, s, o);
    if (lane == 0) dur[warp] = softplus_f(s + b3[0]);
}

// ---------------- length regulator ----------------
__global__ void expand_k(const float* __restrict__ dur, int* __restrict__ idx,
                         float* __restrict__ mask) {
    __shared__ float ends[TE];
    int bb = blockIdx.x;
    int t = threadIdx.x;
    ends[t] = rintf(fmaxf(dur[bb * TE + t], 0.f));
    __syncthreads();
    if (t == 0) {
        float s = 0.f;
        for (int i = 0; i < TE; i++) { s += ends[i]; ends[i] = s; }
    }
    __syncthreads();
    float total = ends[TE - 1];
    for (int tp = t; tp < TD; tp += TE) {
        float fp = (float)tp;
        int lo = 0, hi = TE;
        while (lo < hi) { int mid = (lo + hi) >> 1; if (ends[mid] <= fp) lo = mid + 1; else hi = mid; }
        int id = lo < TE - 1 ? lo : TE - 1;
        idx[bb * TD + tp] = id;
        mask[bb * TD + tp] = fp < total ? 1.f : 0.f;
    }
}
__global__ void gather_k(const float* __restrict__ enc, const int* __restrict__ idx,
                         const float* __restrict__ mask, float* __restrict__ out) {
    int i = blockIdx.x * blockDim.x + threadIdx.x;
    if (i >= MD * DM) return;
    int c = i % DM;
    int r = i / DM;
    int bb = r / TD;
    out[i] = enc[(size_t)(bb * TE + idx[r]) * DM + c] * mask[r];
}

// ---------------- rmsnorm ----------------
__global__ void rmsnorm_k(const float* __restrict__ x, const float* __restrict__ g,
                          float* __restrict__ out) {
    int r = blockIdx.x;
    const float* xr = x + (size_t)r * DM;
    float s = 0.f;
    for (int c = threadIdx.x; c < DM; c += blockDim.x) { float v = xr[c]; s = fmaf(v, v, s); }
    __shared__ float red[4];
    #pragma unroll
    for (int o = 16; o; o >>= 1) s += __shfl_xor_sync(0xffffffffu, s, o);
    int w = threadIdx.x >> 5;
    if ((threadIdx.x & 31) == 0) red[w] = s;
    __syncthreads();
    if (threadIdx.x == 0) red[0] = red[0] + red[1] + red[2] + red[3];
    __syncthreads();
    float scale = rsqrtf(red[0] / (float)DM + 1e-6f);
    for (int c = threadIdx.x; c < DM; c += blockDim.x)
        out[(size_t)r * DM + c] = xr[c] * scale * g[c];
}

// ---------------- mel projection (N=80, bounds-checked) ----------------
__global__ __launch_bounds__(256) void melgemm_k(
    const float* __restrict__ A, const float* __restrict__ W, float* __restrict__ C,
    int M, int N, int K, int lda, int ldb, int ldc, const float* __restrict__ rmask)
{
    __shared__ float As[16][64];
    __shared__ float Bs[16][64];
    const int bm = blockIdx.y * 64, bn = blockIdx.x * 64;
    const int tid = threadIdx.x;
    const int tx = tid & 15, ty = tid >> 4;
    const int am = tid >> 2, ak = (tid & 3) << 2;
    const int bk = tid >> 4, bn4 = (tid & 15) << 2;
    float acc[4][4] = {};
    for (int k0 = 0; k0 < K; k0 += 16) {
        float4 av = make_float4(0.f, 0.f, 0.f, 0.f);
        if (bm + am < M)
            av = *reinterpret_cast<const float4*>(A + (size_t)(bm + am) * lda + k0 + ak);
        As[ak + 0][am] = av.x; As[ak + 1][am] = av.y;
        As[ak + 2][am] = av.z; As[ak + 3][am] = av.w;
        float4 bv;
        const float* wr = W + (size_t)(k0 + bk) * ldb;
        bv.x = (bn + bn4 + 0 < N) ? wr[bn + bn4 + 0] : 0.f;
        bv.y = (bn + bn4 + 1 < N) ? wr[bn + bn4 + 1] : 0.f;
        bv.z = (bn + bn4 + 2 < N) ? wr[bn + bn4 + 2] : 0.f;
        bv.w = (bn + bn4 + 3 < N) ? wr[bn + bn4 + 3] : 0.f;
        Bs[bk][bn4 + 0] = bv.x; Bs[bk][bn4 + 1] = bv.y;
        Bs[bk][bn4 + 2] = bv.z; Bs[bk][bn4 + 3] = bv.w;
        __syncthreads();
        #pragma unroll
        for (int kk = 0; kk < 16; kk++) {
            float af[4], bf[4];
            #pragma unroll
            for (int i = 0; i < 4; i++) af[i] = As[kk][(ty << 2) + i];
            #pragma unroll
            for (int j = 0; j < 4; j++) bf[j] = Bs[kk][(tx << 2) + j];
            #pragma unroll
            for (int i = 0; i < 4; i++)
                #pragma unroll
                for (int j = 0; j < 4; j++)
                    acc[i][j] = fmaf(af[i], bf[j], acc[i][j]);
        }
        __syncthreads();
    }
    #pragma unroll
    for (int i = 0; i < 4; i++) {
        int m = bm + (ty << 2) + i;
        if (m >= M) continue;
        #pragma unroll
        for (int j = 0; j < 4; j++) {
            int n = bn + (tx << 2) + j;
            if (n >= N) continue;
            C[(size_t)m * ldc + n] = acc[i][j] * rmask[m];
        }
    }
}

__global__ void tail_k(float* __restrict__ out, const float* __restrict__ mask, int n) {
    int i = blockIdx.x * blockDim.x + threadIdx.x;
    if (i >= n) return;
    out[i] = (i < NB * TD) ? mask[i] : 0.f;
}

// ---------------- host driver ----------------
extern "C" void kernel_launch(void* const* d_in, const int* in_sizes, int n_in,
                              void* d_out, int out_size) {
    (void)n_in;
    int map[32];
    if (in_sizes[2] == 3 * DM * 2 * DI) {
        for (int i = 0; i < 32; i++) map[i] = i;
    } else {
        const int m[32] = {0, 1,
                           14, 15, 16, 17, 18, 19, 20, 21, 22,
                           2, 3, 4, 5, 6, 7, 8, 9, 10, 11,
                           23, 24, 25, 26, 27, 28, 29, 30, 31,
                           12, 13};
        for (int i = 0; i < 32; i++) map[i] = m[i];
    }
    const int*   text      = (const int*)  d_in[map[0]];
    const float* emb       = (const float*)d_in[map[1]];
    const float* enc_in_w  = (const float*)d_in[map[2]];
    const float* enc_cw    = (const float*)d_in[map[3]];
    const float* enc_cb    = (const float*)d_in[map[4]];
    const float* enc_xpw   = (const float*)d_in[map[5]];
    const float* enc_dtw   = (const float*)d_in[map[6]];
    const float* enc_dtb   = (const float*)d_in[map[7]];
    const float* enc_alog  = (const float*)d_in[map[8]];
    const float* enc_dp    = (const float*)d_in[map[9]];
    const float* enc_ow    = (const float*)d_in[map[10]];
    const float* dp_c1w    = (const float*)d_in[map[11]];
    const float* dp_c1b    = (const float*)d_in[map[12]];
    const float* dp_g1     = (const float*)d_in[map[13]];
    const float* dp_b1     = (const float*)d_in[map[14]];
    const float* dp_c2w    = (const float*)d_in[map[15]];
    const float* dp_c2b    = (const float*)d_in[map[16]];
    const float* dp_g2     = (const float*)d_in[map[17]];
    const float* dp_b2     = (const float*)d_in[map[18]];
    const float* dp_c3w    = (const float*)d_in[map[19]];
    const float* dp_c3b    = (const float*)d_in[map[20]];
    const float* dec_in_w  = (const float*)d_in[map[21]];
    const float* dec_cw    = (const float*)d_in[map[22]];
    const float* dec_cb    = (const float*)d_in[map[23]];
    const float* dec_xpw   = (const float*)d_in[map[24]];
    const float* dec_dtw   = (const float*)d_in[map[25]];
    const float* dec_dtb   = (const float*)d_in[map[26]];
    const float* dec_alog  = (const float*)d_in[map[27]];
    const float* dec_dpv   = (const float*)d_in[map[28]];
    const float* dec_ow    = (const float*)d_in[map[29]];
    const float* norm_g    = (const float*)d_in[map[30]];
    const float* out_w     = (const float*)d_in[map[31]];

    float *x0, *x1, *xz, *u, *xdbl, *part, *delta, *gate, *im, *wt, *h1, *h2, *dur, *mask;
    int* idx;
    cudaGetSymbolAddress((void**)&x0,    g_x0);
    cudaGetSymbolAddress((void**)&x1,    g_x1);
    cudaGetSymbolAddress((void**)&xz,    g_xz);
    cudaGetSymbolAddress((void**)&u,     g_u);
    cudaGetSymbolAddress((void**)&xdbl,  g_xdbl);
    cudaGetSymbolAddress((void**)&part,  g_part);
    cudaGetSymbolAddress((void**)&delta, g_delta);
    cudaGetSymbolAddress((void**)&gate,  g_gate);
    cudaGetSymbolAddress((void**)&im,    g_im2col);
    cudaGetSymbolAddress((void**)&wt,    g_wt);
    cudaGetSymbolAddress((void**)&h1,    g_h1);
    cudaGetSymbolAddress((void**)&h2,    g_h2);
    cudaGetSymbolAddress((void**)&dur,   g_dur);
    cudaGetSymbolAddress((void**)&idx,   g_idx);
    cudaGetSymbolAddress((void**)&mask,  g_mask);

    auto mamba = [&](const float* xin, float* xout, int L, int l,
                     const float* inw, const float* cw, const float* cb,
                     const float* xpw, const float* dtw, const float* dtb,
                     const float* alog, const float* dp, const float* ow) {
        int M = NB * L;
        // in_proj: [M,512] @ [512,2048]
        gemm128_k<0><<<dim3(2 * DI / 128, M / 128), 256>>>(
            xin, inw + (size_t)l * DM * 2 * DI, xz, DM, DM, 2 * DI, 2 * DI, nullptr);
        int tot = M * DI;
        dwconv_silu_k<<<(tot + 255) / 256, 256>>>(xz, cw + (size_t)l * DI * 4,
                                                  cb + (size_t)l * DI, u, L);
        // xproj split-K: [M,1024] @ [1024,64]
        xp_k<<<dim3(M / 64, KS), 256>>>(u, xpw + (size_t)l * DI * 64, part, M);
        xp_reduce_k<<<(M * 16 + 255) / 256, 256>>>(part, xdbl, M);
        // dt: softplus([M,32] @ [32,1024] + b)
        gemm64_k<1><<<dim3(DI / 64, M / 64), 256>>>(
            xdbl, dtw + (size_t)l * DTR * DI, delta, DTR, 64, DI, DI,
            dtb + (size_t)l * DI, nullptr, nullptr);
        scan_k<<<(NB * DI * 4 + 127) / 128, 128>>>(xdbl, delta, u, xz,
                                                   alog + (size_t)l * DI * DS,
                                                   dp + (size_t)l * DI, gate, L);
        // out_proj: [M,1024] @ [1024,512]
        gemm64_k<0><<<dim3(DM / 64, M / 64), 256>>>(
            gate, ow + (size_t)l * DI * DM, xout, DI, DI, DM, DM,
            nullptr, nullptr, nullptr);
    };

    embed_k<<<(ME * DM + 255) / 256, 256>>>(text, emb, x0);

    mamba(x0, x1, TE, 0, enc_in_w, enc_cw, enc_cb, enc_xpw, enc_dtw, enc_dtb, enc_alog, enc_dp, enc_ow);
    mamba(x1, x0, TE, 1, enc_in_w, enc_cw, enc_cb, enc_xpw, enc_dtw, enc_dtb, enc_alog, enc_dp, enc_ow);
    mamba(x0, x1, TE, 2, enc_in_w, enc_cw, enc_cb, enc_xpw, enc_dtw, enc_dtb, enc_alog, enc_dp, enc_ow);

    // duration predictor on x1
    wt_k<<<(DM * DM * 3 + 255) / 256, 256>>>(dp_c1w, wt);
    im2col_k<<<(ME * DM * 3 + 255) / 256, 256>>>(x1, im);
    gemm64_k<2><<<dim3(DM / 64, ME / 64), 256>>>(
        im, wt, h1, 3 * DM, 3 * DM, DM, DM, dp_c1b, dp_g1, dp_b1);
    wt_k<<<(DM * DM * 3 + 255) / 256, 256>>>(dp_c2w, wt);
    im2col_k<<<(ME * DM * 3 + 255) / 256, 256>>>(h1, im);
    gemm64_k<2><<<dim3(DM / 64, ME / 64), 256>>>(
        im, wt, h2, 3 * DM, 3 * DM, DM, DM, dp_c2b, dp_g2, dp_b2);
    dur_k<<<(ME * 32 + 255) / 256, 256>>>(h2, dp_c3w, dp_c3b, dur);

    expand_k<<<NB, TE>>>(dur, idx, mask);
    gather_k<<<(MD * DM + 255) / 256, 256>>>(x1, idx, mask, x0);

    mamba(x0, x1, TD, 0, dec_in_w, dec_cw, dec_cb, dec_xpw, dec_dtw, dec_dtb, dec_alog, dec_dpv, dec_ow);
    mamba(x1, x0, TD, 1, dec_in_w, dec_cw, dec_cb, dec_xpw, dec_dtw, dec_dtb, dec_alog, dec_dpv, dec_ow);
    mamba(x0, x1, TD, 2, dec_in_w, dec_cw, dec_cb, dec_xpw, dec_dtw, dec_dtb, dec_alog, dec_dpv, dec_ow);

    rmsnorm_k<<<MD, 128>>>(x1, norm_g, x0);
    melgemm_k<<<dim3((NM + 63) / 64, MD / 64), 256>>>(
        x0, out_w, (float*)d_out, MD, NM, DM, DM, NM, NM, mask);

    int melN = MD * NM;
    if (out_size > melN) {
        int n = out_size - melN;
        tail_k<<<(n + 255) / 256, 256>>>((float*)d_out + melN, mask, n);
    }
}